// round 8
// baseline (speedup 1.0000x reference)
#include <cuda_runtime.h>
#include <cuda_bf16.h>

// Problem constants
#define B_    64
#define C_    2048
#define HW_   576
#define HW4_  144                 // HW_/4 float4 groups per channel row
#define GRID  296                 // 2 blocks/SM * 148 SMs, all co-resident
#define NT    4096                // 64-channel tiles: 2*B_*(C_/64)
#define TPTB  32                  // tiles per (t,b)

// Scratch (allocation-free rule: __device__ globals; zero-init at load,
// reset at end of every launch -> deterministic replays)
__device__ float4       g_part[GRID][2][HW4_];   // per-(block,segment) partial
__device__ float        g_lum_v[B_][HW_];        // lum_v row-major
__device__ float        g_lum_iT[HW_][B_];       // lum_i TRANSPOSED
__device__ double       g_sum;
__device__ int          g_cnt;
__device__ unsigned int g_ticket;
__device__ unsigned int g_a1, g_d1, g_a2, g_d2;  // grid barrier arrive/depart

// ---------------------------------------------------------------------------
// One persistent kernel. grid = 296, block = 576 (2 blocks/SM exactly ->
// perfect SM balance; 4096 tiles split contiguously -> 98.8% work balance).
// Phase A: barrier-free streaming sum-of-squares; register accumulation
//   across all tiles of a (t,b) group; <=2 groups per block; one smem fold
//   + one float4 partial store per group.
// Barrier 1. Phase B: gather partials per (t,b) by recomputing the static
//   schedule -> lum_v / lum_iT (blocks 0..31, one output per thread).
// Barrier 2. Phase C: pairwise MSE (blocks 0..63, 9 p-slices x 64 j),
//   mask, reduce, finalize (ticket), reset state.
// Labels are int32 (JAX x64 disabled).
// ---------------------------------------------------------------------------
__global__ void __launch_bounds__(576, 2)
k_fused(const float* __restrict__ fv, const float* __restrict__ fi,
        const int* __restrict__ labels, float* __restrict__ out) {
    const int bid  = blockIdx.x;
    const int tid  = threadIdx.x;
    const int q    = tid % HW4_;
    const int csub = tid / HW4_;

    __shared__ float4 sh[4][HW4_];

    // ---- Phase A: streaming over contiguous tile range ----
    {
        const int s = (bid * NT) / GRID;
        const int e = ((bid + 1) * NT) / GRID;
        int seg = 0;
        int tau = s;
        while (tau < e) {
            const int tb   = tau >> 5;               // (t,b) group
            const int gend = min(e, (tb + 1) << 5);
            const int t    = tb >> 6;
            const int b    = tb & 63;
            const float* __restrict__ f = t ? fi : fv;

            float ax = 0.f, ay = 0.f, az = 0.f, aw = 0.f;
            for (int tt = tau; tt < gend; ++tt) {
                const int chunk = tt & 31;           // 64-ch chunk in (t,b)
                const float4* __restrict__ base = (const float4*)
                    (f + ((size_t)b * C_ + (size_t)chunk * 64
                          + (size_t)csub * 16) * HW_) + q;
#pragma unroll
                for (int it = 0; it < 16; ++it) {
                    float4 x = base[(size_t)it * HW4_];
                    ax = fmaf(x.x, x.x, ax);
                    ay = fmaf(x.y, x.y, ay);
                    az = fmaf(x.z, x.z, az);
                    aw = fmaf(x.w, x.w, aw);
                }
            }
            sh[csub][q] = make_float4(ax, ay, az, aw);
            __syncthreads();
            if (csub == 0) {
                float4 a = sh[0][q], c1 = sh[1][q], c2 = sh[2][q], c3 = sh[3][q];
                a.x += c1.x + c2.x + c3.x;
                a.y += c1.y + c2.y + c3.y;
                a.z += c1.z + c2.z + c3.z;
                a.w += c1.w + c2.w + c3.w;
                g_part[bid][seg][q] = a;
            }
            __syncthreads();                         // sh reuse guard
            ++seg;
            tau = gend;
        }
    }

    // ---- Grid barrier 1 ----
    __threadfence();
    __syncthreads();
    if (tid == 0) {
        atomicAdd(&g_a1, 1u);
        while (atomicAdd(&g_a1, 0u) < GRID) __nanosleep(64);
        atomicAdd(&g_d1, 1u);                        // resetter waits on departs
    }
    __syncthreads();

    // ---- Phase B: gather partials -> lum_v / lum_iT (blocks 0..31) ----
    if (bid < 32) {
        const int o  = bid * 576 + tid;              // 0..18431
        const int qq = o % HW4_;
        const int tb = o / HW4_;                     // 0..127
        const int b  = tb & 63;
        const int t  = tb >> 6;

        const int tileLo = tb * TPTB;
        int kmin = (tileLo * GRID) / NT - 1; if (kmin < 0) kmin = 0;
        int kmax = ((tileLo + TPTB - 1) * GRID) / NT + 1;
        if (kmax > GRID - 1) kmax = GRID - 1;

        float4 sacc = make_float4(0.f, 0.f, 0.f, 0.f);
        for (int k = kmin; k <= kmax; ++k) {
            const int sk = (k * NT) / GRID;
            const int ek = ((k + 1) * NT) / GRID;
            const int lo = sk > tileLo ? sk : tileLo;
            const int hi = ek < tileLo + TPTB ? ek : tileLo + TPTB;
            if (lo < hi) {
                const int seg = ((sk >> 5) == tb) ? 0 : 1;
                float4 x = g_part[k][seg][qq];
                sacc.x += x.x; sacc.y += x.y; sacc.z += x.z; sacc.w += x.w;
            }
        }
        if (t == 0) {
            ((float4*)g_lum_v[b])[qq] = sacc;
        } else {
            g_lum_iT[4 * qq + 0][b] = sacc.x;
            g_lum_iT[4 * qq + 1][b] = sacc.y;
            g_lum_iT[4 * qq + 2][b] = sacc.z;
            g_lum_iT[4 * qq + 3][b] = sacc.w;
        }
    }

    // ---- Grid barrier 2 ----
    __threadfence();
    __syncthreads();
    if (tid == 0) {
        atomicAdd(&g_a2, 1u);
        while (atomicAdd(&g_a2, 0u) < GRID) __nanosleep(64);
        atomicAdd(&g_d2, 1u);
    }
    __syncthreads();

    if (bid >= B_) return;                           // non-pair blocks done

    // ---- Phase C: pairwise MSE. i = bid, j = tid%64, slice = tid/64 ----
    const int i  = bid;
    const int j  = tid % 64;
    const int sl = tid / 64;                         // 0..8

    __shared__ float  s_lv[HW_];
    __shared__ double s_vv[9][64], s_cf[9][64], s_sf[9][64];
    __shared__ double s_red[64];

    s_lv[tid] = g_lum_v[i][tid];
    __syncthreads();

    {
        const int p0 = sl * 64;
        float vv0=0.f, cf0=0.f, sf0=0.f, vv1=0.f, cf1=0.f, sf1=0.f;
#pragma unroll
        for (int k = 0; k < 32; ++k) {
            float lv = s_lv[p0 + k];
            float li = g_lum_iT[p0 + k][j];
            vv0 = fmaf(lv, lv, vv0);
            cf0 = fmaf(lv, li, cf0);
            sf0 = fmaf(li, li, sf0);
        }
#pragma unroll
        for (int k = 32; k < 64; ++k) {
            float lv = s_lv[p0 + k];
            float li = g_lum_iT[p0 + k][j];
            vv1 = fmaf(lv, lv, vv1);
            cf1 = fmaf(lv, li, cf1);
            sf1 = fmaf(li, li, sf1);
        }
        s_vv[sl][j] = (double)vv0 + (double)vv1;     // chunked fp32 -> double
        s_cf[sl][j] = (double)cf0 + (double)cf1;
        s_sf[sl][j] = (double)sf0 + (double)sf1;
    }
    __syncthreads();

    bool   m   = false;
    double mse = 0.0;
    if (sl == 0) {
        double vv = 0.0, cf = 0.0, sf = 0.0;
#pragma unroll
        for (int s = 0; s < 9; ++s) {
            vv += s_vv[s][j]; cf += s_cf[s][j]; sf += s_sf[s][j];
        }
        mse = (vv + sf - 2.0 * cf) / (double)HW_;
        m = (labels[i] == labels[j]) && (i != j);
    }
    const int cnt_i = __syncthreads_count(m);        // only sl==0 can be true

    if (sl == 0) s_red[j] = m ? mse : 0.0;
    __syncthreads();
    for (int s = 32; s > 0; s >>= 1) {
        if (tid < s) s_red[tid] += s_red[tid + s];
        __syncthreads();
    }

    if (tid == 0) {
        atomicAdd(&g_sum, s_red[0]);
        atomicAdd(&g_cnt, cnt_i);
        __threadfence();
        const unsigned tk = atomicAdd(&g_ticket, 1u);
        if (tk == B_ - 1) {
            const double total = atomicAdd(&g_sum, 0.0);  // atomic read
            const int    cnt   = atomicAdd(&g_cnt, 0);
            out[0] = (cnt > 0) ? (float)(total / (double)cnt) : 0.0f;
            // wait until every block is fully past both barriers, then reset
            while (atomicAdd(&g_d1, 0u) < GRID) __nanosleep(64);
            while (atomicAdd(&g_d2, 0u) < GRID) __nanosleep(64);
            g_sum = 0.0; g_cnt = 0; g_ticket = 0u;
            g_a1 = 0u; g_d1 = 0u; g_a2 = 0u; g_d2 = 0u;
            __threadfence();
        }
    }
}

extern "C" void kernel_launch(void* const* d_in, const int* in_sizes, int n_in,
                              void* d_out, int out_size) {
    const float* fv     = (const float*)d_in[0];
    const float* fi     = (const float*)d_in[1];
    const int*   labels = (const int*)d_in[2];
    float*       out    = (float*)d_out;

    k_fused<<<GRID, 576>>>(fv, fi, labels, out);
}

// round 9
// speedup vs baseline: 1.0164x; 1.0164x over previous
#include <cuda_runtime.h>
#include <cuda_bf16.h>

// Problem constants
#define B_    64
#define C_    2048
#define HW_   576
#define HW4_  144          // HW_/4 float4 groups per channel row
#define NBLK  16           // k1 tiles per (t,b): 128 channels each
#define CPS   32           // channels per (block, csub)

// Scratch (allocation-free rule: __device__ globals)
__device__ float4       g_part4[2][B_][NBLK][HW4_]; // per-tile partial (4.7 MB)
__device__ float        g_lum_v[B_][HW_];           // lum_v row-major
__device__ float        g_lum_iT[HW_][B_];          // lum_i TRANSPOSED
__device__ double       g_sum;
__device__ int          g_cnt;
__device__ unsigned int g_ticket;
__device__ int          g_arrive;                   // k2 grid barrier

// ---------------------------------------------------------------------------
// Kernel 1: streaming sum-of-squares, float4 loads, smem fold -> one float4
// partial per (tile,q). grid = (NBLK, B, 2), block = 576, 3 blocks/SM.
// Proven ~87 us (R5 k1). Also resets reduction state for this replay
// (k1 completes before k2 starts -> no race).
// ---------------------------------------------------------------------------
__global__ void __launch_bounds__(576, 3)
k_lum_partial(const float* __restrict__ fv, const float* __restrict__ fi) {
    const int blk  = blockIdx.x;
    const int b    = blockIdx.y;
    const int t    = blockIdx.z;
    const int tid  = threadIdx.x;
    const int q    = tid % HW4_;
    const int csub = tid / HW4_;

    if (blk == 0 && b == 0 && t == 0 && tid == 0) {
        g_sum = 0.0; g_cnt = 0; g_ticket = 0u; g_arrive = 0;
    }

    const float* __restrict__ f = t ? fi : fv;
    const float4* __restrict__ base = (const float4*)
        (f + ((size_t)b * C_ + (size_t)blk * 128) * HW_)
        + (size_t)csub * CPS * HW4_ + q;

    float ax = 0.f, ay = 0.f, az = 0.f, aw = 0.f;
#pragma unroll 8
    for (int it = 0; it < CPS; ++it) {
        float4 x = base[(size_t)it * HW4_];
        ax = fmaf(x.x, x.x, ax);
        ay = fmaf(x.y, x.y, ay);
        az = fmaf(x.z, x.z, az);
        aw = fmaf(x.w, x.w, aw);
    }

    __shared__ float4 sh[4][HW4_];
    sh[csub][q] = make_float4(ax, ay, az, aw);
    __syncthreads();

    if (csub == 0) {
        float4 a = sh[0][q], c1 = sh[1][q], c2 = sh[2][q], c3 = sh[3][q];
        a.x += c1.x + c2.x + c3.x;
        a.y += c1.y + c2.y + c3.y;
        a.z += c1.z + c2.z + c3.z;
        a.w += c1.w + c2.w + c3.w;
        g_part4[t][b][blk][q] = a;
    }
}

// ---------------------------------------------------------------------------
// Kernel 2 (fused fold + pair): grid = 64, block = 576 (36864 threads).
// Fold: one float4 output per thread (18432 outputs), L2-hot coalesced.
// Grid barrier (g_arrive reset by k1 -> no replay race; 64 blocks always
// co-resident -> no deadlock). Pair: i = bid, 9 p-slices x 64 j, chunked
// fp32 -> double, mask, reduce, ticket finalize.
// Labels are int32 (JAX x64 disabled).
// ---------------------------------------------------------------------------
__global__ void __launch_bounds__(576, 2)
k_fold_pair(const int* __restrict__ labels, float* __restrict__ out) {
    const int bid = blockIdx.x;   // 0..63
    const int tid = threadIdx.x;  // 0..575

    // ---- Phase 1: fold (first 18432 of 36864 threads, one output each) ----
    {
        const int o = bid * 576 + tid;
        if (o < 2 * B_ * HW4_) {
            const int qq = o % HW4_;
            const int tb = o / HW4_;
            const int b  = tb % B_;
            const int t  = tb / B_;
            float4 s = make_float4(0.f, 0.f, 0.f, 0.f);
#pragma unroll
            for (int c = 0; c < NBLK; ++c) {
                float4 x = g_part4[t][b][c][qq];
                s.x += x.x; s.y += x.y; s.z += x.z; s.w += x.w;
            }
            if (t == 0) {
                ((float4*)g_lum_v[b])[qq] = s;
            } else {
                g_lum_iT[4 * qq + 0][b] = s.x;
                g_lum_iT[4 * qq + 1][b] = s.y;
                g_lum_iT[4 * qq + 2][b] = s.z;
                g_lum_iT[4 * qq + 3][b] = s.w;
            }
        }
    }

    // ---- Grid barrier over 64 co-resident blocks ----
    __threadfence();
    __syncthreads();
    if (tid == 0) {
        atomicAdd(&g_arrive, 1);
        while (atomicAdd(&g_arrive, 0) < B_) __nanosleep(32);
    }
    __syncthreads();

    // ---- Phase 2: pairwise MSE. i = bid, j = tid%64, slice = tid/64 ----
    const int i  = bid;
    const int j  = tid % 64;
    const int sl = tid / 64;      // 0..8

    __shared__ float  s_lv[HW_];
    __shared__ double s_vv[9][64], s_cf[9][64], s_sf[9][64];
    __shared__ double s_red[64];

    s_lv[tid] = g_lum_v[i][tid];
    __syncthreads();

    {
        const int p0 = sl * 64;
        float vv0=0.f, cf0=0.f, sf0=0.f, vv1=0.f, cf1=0.f, sf1=0.f;
#pragma unroll
        for (int k = 0; k < 32; ++k) {
            float lv = s_lv[p0 + k];
            float li = g_lum_iT[p0 + k][j];
            vv0 = fmaf(lv, lv, vv0);
            cf0 = fmaf(lv, li, cf0);
            sf0 = fmaf(li, li, sf0);
        }
#pragma unroll
        for (int k = 32; k < 64; ++k) {
            float lv = s_lv[p0 + k];
            float li = g_lum_iT[p0 + k][j];
            vv1 = fmaf(lv, lv, vv1);
            cf1 = fmaf(lv, li, cf1);
            sf1 = fmaf(li, li, sf1);
        }
        s_vv[sl][j] = (double)vv0 + (double)vv1;   // chunked fp32 -> double
        s_cf[sl][j] = (double)cf0 + (double)cf1;
        s_sf[sl][j] = (double)sf0 + (double)sf1;
    }
    __syncthreads();

    bool   m   = false;
    double mse = 0.0;
    if (sl == 0) {
        double vv = 0.0, cf = 0.0, sf = 0.0;
#pragma unroll
        for (int s = 0; s < 9; ++s) {
            vv += s_vv[s][j]; cf += s_cf[s][j]; sf += s_sf[s][j];
        }
        mse = (vv + sf - 2.0 * cf) / (double)HW_;
        m = (labels[i] == labels[j]) && (i != j);
    }
    const int cnt_i = __syncthreads_count(m);      // only sl==0 can be true

    if (sl == 0) s_red[j] = m ? mse : 0.0;
    __syncthreads();
    for (int s = 32; s > 0; s >>= 1) {
        if (tid < s) s_red[tid] += s_red[tid + s];
        __syncthreads();
    }

    if (tid == 0) {
        atomicAdd(&g_sum, s_red[0]);
        atomicAdd(&g_cnt, cnt_i);
        __threadfence();
        const unsigned tk = atomicAdd(&g_ticket, 1u);
        if (tk == B_ - 1) {
            const double total = atomicAdd(&g_sum, 0.0);  // atomic read
            const int    cnt   = atomicAdd(&g_cnt, 0);
            out[0] = (cnt > 0) ? (float)(total / (double)cnt) : 0.0f;
        }
    }
}

extern "C" void kernel_launch(void* const* d_in, const int* in_sizes, int n_in,
                              void* d_out, int out_size) {
    const float* fv     = (const float*)d_in[0];
    const float* fi     = (const float*)d_in[1];
    const int*   labels = (const int*)d_in[2];
    float*       out    = (float*)d_out;

    k_lum_partial<<<dim3(NBLK, B_, 2), 576>>>(fv, fi);
    k_fold_pair<<<B_, 576>>>(labels, out);
}

// round 10
// speedup vs baseline: 1.0212x; 1.0047x over previous
#include <cuda_runtime.h>
#include <cuda_bf16.h>

// Problem constants
#define B_    64
#define C_    2048
#define HW_   576
#define HW4_  144          // HW_/4 float4 groups per channel row
#define NBLK  16           // k1 tiles per (t,b): 128 channels each
#define CPS   32           // channels per (block, csub)
#define K2GRID 128         // k2 blocks: one per (t,b)

// Scratch (allocation-free rule: __device__ globals)
__device__ float4       g_part4[2][B_][NBLK][HW4_]; // per-tile partial (4.7 MB)
__device__ float        g_lum_iT[HW_][B_];          // lum_i TRANSPOSED
__device__ double       g_sum;
__device__ int          g_cnt;
__device__ unsigned int g_ticket;
__device__ int          g_arrive;                   // k2 grid barrier

// ---------------------------------------------------------------------------
// Kernel 1 (FROZEN, proven ~87 us): streaming sum-of-squares, float4 loads,
// smem fold -> one float4 partial per (tile,q). grid = (NBLK, B, 2),
// block = 576, 3 blocks/SM. Also resets reduction state for this replay.
// ---------------------------------------------------------------------------
__global__ void __launch_bounds__(576, 3)
k_lum_partial(const float* __restrict__ fv, const float* __restrict__ fi) {
    const int blk  = blockIdx.x;
    const int b    = blockIdx.y;
    const int t    = blockIdx.z;
    const int tid  = threadIdx.x;
    const int q    = tid % HW4_;
    const int csub = tid / HW4_;

    if (blk == 0 && b == 0 && t == 0 && tid == 0) {
        g_sum = 0.0; g_cnt = 0; g_ticket = 0u; g_arrive = 0;
    }

    const float* __restrict__ f = t ? fi : fv;
    const float4* __restrict__ base = (const float4*)
        (f + ((size_t)b * C_ + (size_t)blk * 128) * HW_)
        + (size_t)csub * CPS * HW4_ + q;

    float ax = 0.f, ay = 0.f, az = 0.f, aw = 0.f;
#pragma unroll 8
    for (int it = 0; it < CPS; ++it) {
        float4 x = base[(size_t)it * HW4_];
        ax = fmaf(x.x, x.x, ax);
        ay = fmaf(x.y, x.y, ay);
        az = fmaf(x.z, x.z, az);
        aw = fmaf(x.w, x.w, aw);
    }

    __shared__ float4 sh[4][HW4_];
    sh[csub][q] = make_float4(ax, ay, az, aw);
    __syncthreads();

    if (csub == 0) {
        float4 a = sh[0][q], c1 = sh[1][q], c2 = sh[2][q], c3 = sh[3][q];
        a.x += c1.x + c2.x + c3.x;
        a.y += c1.y + c2.y + c3.y;
        a.z += c1.z + c2.z + c3.z;
        a.w += c1.w + c2.w + c3.w;
        g_part4[t][b][blk][q] = a;
    }
}

// ---------------------------------------------------------------------------
// Kernel 2: grid = 128, block = 576 (2/SM, all co-resident).
// Fold: block bid owns (t,b) = (bid>>6, bid&63). All 576 threads load:
//   part = tid/144 folds 4 tiles, 4-way smem reduce. t=0 blocks keep
//   lum_v[b] in their OWN smem (sole consumer); t=1 blocks write lum_iT.
// Barrier (g_arrive, reset by k1). t=1 blocks exit after arriving.
// Pair: blocks 0..63, i = bid, 9 p-slices x 64 j, chunked fp32 -> double,
//   mask, reduce, ticket finalize. Labels are int32 (JAX x64 disabled).
// ---------------------------------------------------------------------------
__global__ void __launch_bounds__(576, 2)
k_fold_pair(const int* __restrict__ labels, float* __restrict__ out) {
    const int bid = blockIdx.x;   // 0..127
    const int tid = threadIdx.x;  // 0..575

    __shared__ float  s_lv[HW_];
    __shared__ float4 s_fold[4][HW4_];

    // ---- Phase 1: fold (all threads; 4 loads each) ----
    {
        const int t    = bid >> 6;
        const int b    = bid & 63;
        const int qq   = tid % HW4_;
        const int part = tid / HW4_;        // 0..3, folds tiles [4p, 4p+4)

        float4 a = make_float4(0.f, 0.f, 0.f, 0.f);
#pragma unroll
        for (int c = part * 4; c < part * 4 + 4; ++c) {
            float4 x = g_part4[t][b][c][qq];
            a.x += x.x; a.y += x.y; a.z += x.z; a.w += x.w;
        }
        s_fold[part][qq] = a;
        __syncthreads();

        if (part == 0) {
            float4 s0 = s_fold[0][qq], s1 = s_fold[1][qq];
            float4 s2 = s_fold[2][qq], s3 = s_fold[3][qq];
            float4 s  = make_float4(s0.x + s1.x + s2.x + s3.x,
                                    s0.y + s1.y + s2.y + s3.y,
                                    s0.z + s1.z + s2.z + s3.z,
                                    s0.w + s1.w + s2.w + s3.w);
            if (t == 0) {
                ((float4*)s_lv)[qq] = s;        // stays local: only consumer
            } else {
                g_lum_iT[4 * qq + 0][b] = s.x;
                g_lum_iT[4 * qq + 1][b] = s.y;
                g_lum_iT[4 * qq + 2][b] = s.z;
                g_lum_iT[4 * qq + 3][b] = s.w;
            }
        }
    }

    // ---- Grid barrier over 128 co-resident blocks ----
    __threadfence();
    __syncthreads();
    if (tid == 0) atomicAdd(&g_arrive, 1);
    if (bid >= B_) return;                  // lum_iT producers done
    if (tid == 0) {
        while (atomicAdd(&g_arrive, 0) < K2GRID) __nanosleep(32);
    }
    __syncthreads();

    // ---- Phase 2: pairwise MSE. i = bid, j = tid%64, slice = tid/64 ----
    const int i  = bid;
    const int j  = tid % 64;
    const int sl = tid / 64;                // 0..8

    __shared__ double s_vv[9][64], s_cf[9][64], s_sf[9][64];
    __shared__ double s_red[64];

    {
        const int p0 = sl * 64;
        float vv0=0.f, cf0=0.f, sf0=0.f, vv1=0.f, cf1=0.f, sf1=0.f;
#pragma unroll
        for (int k = 0; k < 32; ++k) {
            float lv = s_lv[p0 + k];
            float li = g_lum_iT[p0 + k][j];
            vv0 = fmaf(lv, lv, vv0);
            cf0 = fmaf(lv, li, cf0);
            sf0 = fmaf(li, li, sf0);
        }
#pragma unroll
        for (int k = 32; k < 64; ++k) {
            float lv = s_lv[p0 + k];
            float li = g_lum_iT[p0 + k][j];
            vv1 = fmaf(lv, lv, vv1);
            cf1 = fmaf(lv, li, cf1);
            sf1 = fmaf(li, li, sf1);
        }
        s_vv[sl][j] = (double)vv0 + (double)vv1;   // chunked fp32 -> double
        s_cf[sl][j] = (double)cf0 + (double)cf1;
        s_sf[sl][j] = (double)sf0 + (double)sf1;
    }
    __syncthreads();

    bool   m   = false;
    double mse = 0.0;
    if (sl == 0) {
        double vv = 0.0, cf = 0.0, sf = 0.0;
#pragma unroll
        for (int s = 0; s < 9; ++s) {
            vv += s_vv[s][j]; cf += s_cf[s][j]; sf += s_sf[s][j];
        }
        mse = (vv + sf - 2.0 * cf) / (double)HW_;
        m = (labels[i] == labels[j]) && (i != j);
    }
    const int cnt_i = __syncthreads_count(m);      // only sl==0 can be true

    if (sl == 0) s_red[j] = m ? mse : 0.0;
    __syncthreads();
    for (int s = 32; s > 0; s >>= 1) {
        if (tid < s) s_red[tid] += s_red[tid + s];
        __syncthreads();
    }

    if (tid == 0) {
        atomicAdd(&g_sum, s_red[0]);
        atomicAdd(&g_cnt, cnt_i);
        __threadfence();
        const unsigned tk = atomicAdd(&g_ticket, 1u);
        if (tk == B_ - 1) {
            const double total = atomicAdd(&g_sum, 0.0);  // atomic read
            const int    cnt   = atomicAdd(&g_cnt, 0);
            out[0] = (cnt > 0) ? (float)(total / (double)cnt) : 0.0f;
        }
    }
}

extern "C" void kernel_launch(void* const* d_in, const int* in_sizes, int n_in,
                              void* d_out, int out_size) {
    const float* fv     = (const float*)d_in[0];
    const float* fi     = (const float*)d_in[1];
    const int*   labels = (const int*)d_in[2];
    float*       out    = (float*)d_out;

    k_lum_partial<<<dim3(NBLK, B_, 2), 576>>>(fv, fi);
    k_fold_pair<<<K2GRID, 576>>>(labels, out);
}

// round 11
// speedup vs baseline: 1.0449x; 1.0233x over previous
#include <cuda_runtime.h>
#include <cuda_bf16.h>

// Problem constants
#define B_    64
#define C_    2048
#define HW_   576
#define HW4_  144          // HW_/4 float4 groups per channel row
#define NBLK  16           // k1 tiles per (t,b): 128 channels each
#define CPS   32           // channels per (block, csub)
#define LUMN  (B_ * HW_)   // 36864 floats per lum buffer

// Scratch (allocation-free rule: __device__ globals; zero at module load).
// Parity ping-pong: k1(N) accumulates buf[par], zeroes buf[1-par];
// k2(N) reads buf[par], flips par. Invariant: buf[par] is zero when k1 starts.
__device__ float        g_lum[2][B_][HW_];    // lum_v row-major
__device__ float        g_lumT[2][HW_][B_];   // lum_i TRANSPOSED
__device__ int          g_parity;
__device__ double       g_sum;
__device__ int          g_cnt;
__device__ unsigned int g_ticket;

// ---------------------------------------------------------------------------
// Kernel 1: streaming sum-of-squares (proven ~87us pattern), float4 loads,
// smem fold, then REDG.F32 atomicAdd of the per-tile fold directly into
// g_lum / g_lumT (16 adds per address across the launch). Fire-and-forget:
// stream unaffected. Also zeroes the OTHER parity buffer (36 floats/block)
// and resets the scalar reduction state.
// grid = (NBLK, B, 2), block = 576, 3 blocks/SM.
// ---------------------------------------------------------------------------
__global__ void __launch_bounds__(576, 3)
k_lum_partial(const float* __restrict__ fv, const float* __restrict__ fi) {
    const int blk  = blockIdx.x;
    const int b    = blockIdx.y;
    const int t    = blockIdx.z;
    const int tid  = threadIdx.x;
    const int q    = tid % HW4_;
    const int csub = tid / HW4_;

    const int par = g_parity;

    if (blk == 0 && b == 0 && t == 0 && tid == 0) {
        g_sum = 0.0; g_cnt = 0; g_ticket = 0u;
    }

    // Zero the other parity buffer: 2*LUMN floats over 2048 blocks = 36 each.
    {
        const int blin = blk + NBLK * (b + B_ * t);      // 0..2047
        const int idx  = blin * 36 + tid;
        if (tid < 36) {
            if (idx < LUMN) ((float*)g_lum[1 - par])[idx]         = 0.0f;
            else            ((float*)g_lumT[1 - par])[idx - LUMN] = 0.0f;
        }
    }

    const float* __restrict__ f = t ? fi : fv;
    const float4* __restrict__ base = (const float4*)
        (f + ((size_t)b * C_ + (size_t)blk * 128) * HW_)
        + (size_t)csub * CPS * HW4_ + q;

    float ax = 0.f, ay = 0.f, az = 0.f, aw = 0.f;
#pragma unroll 8
    for (int it = 0; it < CPS; ++it) {
        float4 x = base[(size_t)it * HW4_];
        ax = fmaf(x.x, x.x, ax);
        ay = fmaf(x.y, x.y, ay);
        az = fmaf(x.z, x.z, az);
        aw = fmaf(x.w, x.w, aw);
    }

    __shared__ float4 sh[4][HW4_];
    sh[csub][q] = make_float4(ax, ay, az, aw);
    __syncthreads();

    if (csub == 0) {
        float4 a = sh[0][q], c1 = sh[1][q], c2 = sh[2][q], c3 = sh[3][q];
        a.x += c1.x + c2.x + c3.x;
        a.y += c1.y + c2.y + c3.y;
        a.z += c1.z + c2.z + c3.z;
        a.w += c1.w + c2.w + c3.w;
        if (t == 0) {
            float* dst = &g_lum[par][b][4 * q];
            atomicAdd(dst + 0, a.x);
            atomicAdd(dst + 1, a.y);
            atomicAdd(dst + 2, a.z);
            atomicAdd(dst + 3, a.w);
        } else {
            atomicAdd(&g_lumT[par][4 * q + 0][b], a.x);
            atomicAdd(&g_lumT[par][4 * q + 1][b], a.y);
            atomicAdd(&g_lumT[par][4 * q + 2][b], a.z);
            atomicAdd(&g_lumT[par][4 * q + 3][b], a.w);
        }
    }
}

// ---------------------------------------------------------------------------
// Kernel 2: PAIR-ONLY (no fold, no grid barrier). grid = 64, block = 576.
// i = bid, j = tid%64, slice = tid/64 (9 p-slices). Chunked fp32 -> double.
// Ticket block finalizes the loss and flips parity (all blocks' parity
// reads precede the flip: ticket==63 implies every block passed its reads).
// Labels are int32 (JAX x64 disabled).
// ---------------------------------------------------------------------------
__global__ void __launch_bounds__(576, 2)
k_pair(const int* __restrict__ labels, float* __restrict__ out) {
    const int i   = blockIdx.x;   // 0..63
    const int tid = threadIdx.x;  // 0..575
    const int j   = tid % 64;
    const int sl  = tid / 64;     // 0..8

    const int par = g_parity;

    __shared__ float  s_lv[HW_];
    __shared__ double s_vv[9][64], s_cf[9][64], s_sf[9][64];
    __shared__ double s_red[64];

    s_lv[tid] = g_lum[par][i][tid];
    __syncthreads();

    {
        const int p0 = sl * 64;
        float vv0=0.f, cf0=0.f, sf0=0.f, vv1=0.f, cf1=0.f, sf1=0.f;
#pragma unroll
        for (int k = 0; k < 32; ++k) {
            float lv = s_lv[p0 + k];
            float li = g_lumT[par][p0 + k][j];
            vv0 = fmaf(lv, lv, vv0);
            cf0 = fmaf(lv, li, cf0);
            sf0 = fmaf(li, li, sf0);
        }
#pragma unroll
        for (int k = 32; k < 64; ++k) {
            float lv = s_lv[p0 + k];
            float li = g_lumT[par][p0 + k][j];
            vv1 = fmaf(lv, lv, vv1);
            cf1 = fmaf(lv, li, cf1);
            sf1 = fmaf(li, li, sf1);
        }
        s_vv[sl][j] = (double)vv0 + (double)vv1;   // chunked fp32 -> double
        s_cf[sl][j] = (double)cf0 + (double)cf1;
        s_sf[sl][j] = (double)sf0 + (double)sf1;
    }
    __syncthreads();

    bool   m   = false;
    double mse = 0.0;
    if (sl == 0) {
        double vv = 0.0, cf = 0.0, sf = 0.0;
#pragma unroll
        for (int s = 0; s < 9; ++s) {
            vv += s_vv[s][j]; cf += s_cf[s][j]; sf += s_sf[s][j];
        }
        mse = (vv + sf - 2.0 * cf) / (double)HW_;
        m = (labels[i] == labels[j]) && (i != j);
    }
    const int cnt_i = __syncthreads_count(m);      // only sl==0 can be true

    if (sl == 0) s_red[j] = m ? mse : 0.0;
    __syncthreads();
    for (int s = 32; s > 0; s >>= 1) {
        if (tid < s) s_red[tid] += s_red[tid + s];
        __syncthreads();
    }

    if (tid == 0) {
        atomicAdd(&g_sum, s_red[0]);
        atomicAdd(&g_cnt, cnt_i);
        __threadfence();
        const unsigned tk = atomicAdd(&g_ticket, 1u);
        if (tk == B_ - 1) {
            const double total = atomicAdd(&g_sum, 0.0);  // atomic read
            const int    cnt   = atomicAdd(&g_cnt, 0);
            out[0] = (cnt > 0) ? (float)(total / (double)cnt) : 0.0f;
            g_parity = par ^ 1;                           // flip for next replay
            __threadfence();
        }
    }
}

extern "C" void kernel_launch(void* const* d_in, const int* in_sizes, int n_in,
                              void* d_out, int out_size) {
    const float* fv     = (const float*)d_in[0];
    const float* fi     = (const float*)d_in[1];
    const int*   labels = (const int*)d_in[2];
    float*       out    = (float*)d_out;

    k_lum_partial<<<dim3(NBLK, B_, 2), 576>>>(fv, fi);
    k_pair<<<B_, 576>>>(labels, out);
}